// round 15
// baseline (speedup 1.0000x reference)
#include <cuda_runtime.h>

// ---------------------------------------------------------------------------
// Model_19095424598065 v15 : algebraically reduced graph-spectral net.
// vs v12 (549us kernel): mode_gemm moved to tensor cores via
// mma.m16n8k8.tf32 with 3xTF32 (hi/lo split) for fp32-class accuracy.
//   F^T[c][t] = M_k^T[c][i] @ XF_k^T[i][t],  N=8 tiles = exact n8.
// M pre-packed hi/lo in a-fragment order (1 coalesced LDG.128 per frag).
// B (XF) preloaded to registers (in-place sFX safe). Stages A/C/E = v12.
// ---------------------------------------------------------------------------

typedef unsigned long long u64t;
typedef unsigned int u32t;

#define NT 256
#define TT 8

// A-fragment-packed M (hi/lo tf32 bits): [k][cblk][kblk][lane][slot]
__device__ u32t d_MA0h[8 * 8 * 16 * 32 * 4];
__device__ u32t d_MA0l[8 * 8 * 16 * 32 * 4];
__device__ u32t d_MA2h[8 * 8 * 16 * 32 * 4];
__device__ u32t d_MA2l[8 * 8 * 16 * 32 * 4];
__device__ float d_tv[8];
__device__ float d_b1[128];
__device__ float d_b3[128];

// ------------------------------ helpers ------------------------------------
static __device__ __forceinline__ u64t dup2(float x) {
    u64t r; asm("mov.b64 %0, {%1, %1};" : "=l"(r) : "f"(x)); return r;
}
static __device__ __forceinline__ u64t pack2(float a, float b) {
    u64t r; asm("mov.b64 %0, {%1, %2};" : "=l"(r) : "f"(a), "f"(b)); return r;
}
static __device__ __forceinline__ void unpack2(u64t v, float& a, float& b) {
    asm("mov.b64 {%0, %1}, %2;" : "=f"(a), "=f"(b) : "l"(v));
}
static __device__ __forceinline__ void fma2(u64t& d, u64t a, u64t b) {
    asm("fma.rn.f32x2 %0, %1, %2, %3;" : "=l"(d) : "l"(a), "l"(b), "l"(d));
}
static __device__ __forceinline__ u64t add2(u64t a, u64t b) {
    u64t r; asm("add.rn.f32x2 %0, %1, %2;" : "=l"(r) : "l"(a), "l"(b)); return r;
}
static __device__ __forceinline__ u32t to_tf32(float f) {
    u32t u; asm("cvt.rna.tf32.f32 %0, %1;" : "=r"(u) : "f"(f)); return u;
}
static __device__ __forceinline__ void mma_tf32(float& c0, float& c1,
                                                float& c2, float& c3,
                                                u32t a0, u32t a1, u32t a2, u32t a3,
                                                u32t b0, u32t b1) {
    asm volatile(
        "mma.sync.aligned.m16n8k8.row.col.f32.tf32.tf32.f32 "
        "{%0,%1,%2,%3}, {%4,%5,%6,%7}, {%8,%9}, {%0,%1,%2,%3};"
        : "+f"(c0), "+f"(c1), "+f"(c2), "+f"(c3)
        : "r"(a0), "r"(a1), "r"(a2), "r"(a3), "r"(b0), "r"(b1));
}

// --------------------------- fused precompute ------------------------------
// 256 blocks: b<128 -> stage0 K-row b; b>=128 -> stage2 K-row b-128.
// Computes M_k[i][c] = sum_j w[i,j,k](Ws[j,c]+lam_k Wn[j,c]) and scatters
// hi/lo tf32 into a-fragment order for A = M_k^T (row c_r=16, col i_r=8).
__global__ void pre_kernel(const float* __restrict__ U, const float* __restrict__ adj,
                           const float* __restrict__ w0, const float* __restrict__ w2,
                           const float* __restrict__ Ws1, const float* __restrict__ Wn1,
                           const float* __restrict__ Ws3, const float* __restrict__ Wn3,
                           const float* __restrict__ bs1, const float* __restrict__ bn1,
                           const float* __restrict__ bs3, const float* __restrict__ bn3)
{
    __shared__ float sw[1024];
    __shared__ float spart[128];
    __shared__ float slam[8];
    const int b = blockIdx.x, c = threadIdx.x;
    const int which = b >> 7, i = b & 127;
    const float* w  = which ? w2  : w0;
    const float* Ws = which ? Ws3 : Ws1;
    const float* Wn = which ? Wn3 : Wn1;

    {
        const int k = c >> 4, s = c & 15;
        float part = 0.f;
        for (int n = s; n < 64; n += 16) {
            float g = 0.f;
            for (int m = 0; m < 64; m++) g += adj[n * 64 + m] * U[m * 64 + k];
            part += U[n * 64 + k] * g;
        }
        spart[c] = part;
    }
    for (int idx = c; idx < 1024; idx += 128) sw[idx] = w[i * 1024 + idx];
    __syncthreads();
    if (c < 8) {
        float lam = 0.f;
        for (int s = 0; s < 16; s++) lam += spart[c * 16 + s];
        slam[c] = lam;
    }
    if (b == 0) {
        if (c < 128) { d_b1[c] = bs1[c] + bn1[c]; d_b3[c] = bs3[c] + bn3[c]; }
        if (c < 8) {
            float ts = 0.f;
            for (int n = 0; n < 64; n++) ts += U[n * 64 + c];
            d_tv[c] = ts;
        }
    }
    __syncthreads();

    float lam[8], acc[8];
#pragma unroll
    for (int k = 0; k < 8; k++) { lam[k] = slam[k]; acc[k] = 0.f; }
#pragma unroll 2
    for (int j = 0; j < 128; j++) {
        float ws = __ldg(Ws + j * 128 + c);
        float wn = __ldg(Wn + j * 128 + c);
#pragma unroll
        for (int k = 0; k < 8; k++)
            acc[k] += sw[j * 8 + k] * fmaf(lam[k], wn, ws);
    }
    // Scatter into a-fragment layout. For value M_k[i][c] (A element (c,i)):
    //   cblk=c>>4, c_r=c&15, kblk=i>>3, i_r=i&7
    //   g=c_r&7, half=c_r>>3, slot=half+2*(i_r>>2), tig=i_r&3, lane=4g+tig
    u32t* MH = which ? d_MA2h : d_MA0h;
    u32t* ML = which ? d_MA2l : d_MA0l;
    const int cblk = c >> 4, c_r = c & 15, kblk = i >> 3, i_r = i & 7;
    const int g = c_r & 7, half = c_r >> 3;
    const int slot = half + 2 * (i_r >> 2);
    const int lane = g * 4 + (i_r & 3);
#pragma unroll
    for (int k = 0; k < 8; k++) {
        float v = acc[k];
        u32t hb = to_tf32(v);
        u32t lb = to_tf32(v - __uint_as_float(hb));
        const int idx = (((k * 8 + cblk) * 16 + kblk) * 32 + lane) * 4 + slot;
        MH[idx] = hb;
        ML[idx] = lb;
    }
}

// ------------------------------- main kernel -------------------------------
// smem (floats): identical to v12.
#define O_FX  0
#define O_UM  8192
#define O_WP  8704
#define O_V   9728
#define O_Y   10752
#define O_WOB 11264
#define SMEMF 12288

// mode_gemm via tensor cores. Warp k owns mode k.
// F^T[c][t] = sum_i M_k^T[c][i] * XF_k[t][i] with m16n8k8 tf32 (3xTF32).
static __device__ __forceinline__ void mode_gemm(const u32t* __restrict__ MH,
                                                 const u32t* __restrict__ ML,
                                                 float* sFX, int tid)
{
    const int k = tid >> 5, lane = tid & 31;
    const int g = lane >> 2, tig = lane & 3;

    // ---- preload B fragments (XF^T) hi/lo; in-place stores become safe ----
    // b0 = XF[t=g][i=kb*8+tig], b1 = XF[t=g][i=kb*8+tig+4]
    u32t bh[32], bl[32];
    {
        const float* xb = sFX + (g * 8 + k) * 128 + tig;
#pragma unroll
        for (int kb = 0; kb < 16; kb++) {
            float v0 = xb[kb * 8];
            float v1 = xb[kb * 8 + 4];
            u32t h0 = to_tf32(v0), h1 = to_tf32(v1);
            bh[2 * kb] = h0; bh[2 * kb + 1] = h1;
            bl[2 * kb]     = to_tf32(v0 - __uint_as_float(h0));
            bl[2 * kb + 1] = to_tf32(v1 - __uint_as_float(h1));
        }
    }

    const uint4* MAh = (const uint4*)MH + (k * 8) * 16 * 32;
    const uint4* MAl = (const uint4*)ML + (k * 8) * 16 * 32;

#pragma unroll 1
    for (int cblk = 0; cblk < 8; cblk++) {
        float c0 = 0.f, c1 = 0.f, c2 = 0.f, c3 = 0.f;
#pragma unroll 4
        for (int kb = 0; kb < 16; kb++) {
            const int fo = (cblk * 16 + kb) * 32 + lane;
            uint4 Ah = __ldg(&MAh[fo]);
            uint4 Al = __ldg(&MAl[fo]);
            mma_tf32(c0, c1, c2, c3, Ah.x, Ah.y, Ah.z, Ah.w, bh[2 * kb], bh[2 * kb + 1]);
            mma_tf32(c0, c1, c2, c3, Ah.x, Ah.y, Ah.z, Ah.w, bl[2 * kb], bl[2 * kb + 1]);
            mma_tf32(c0, c1, c2, c3, Al.x, Al.y, Al.z, Al.w, bh[2 * kb], bh[2 * kb + 1]);
        }
        // c-frag: c0:(row=g, col=2*tig) c1:(g,2*tig+1) c2:(g+8,2*tig) c3:(g+8,2*tig+1)
        // F value at sFX[(t*8+k)*128 + c],  c = cblk*16 + row, t = col
        const int cl = cblk * 16 + g;
        sFX[((2 * tig)     * 8 + k) * 128 + cl]     = c0;
        sFX[((2 * tig + 1) * 8 + k) * 128 + cl]     = c1;
        sFX[((2 * tig)     * 8 + k) * 128 + cl + 8] = c2;
        sFX[((2 * tig + 1) * 8 + k) * 128 + cl + 8] = c3;
    }
}

// Stage C (v12 verbatim).
static __device__ __forceinline__ void tile_stageC(float* sFX, const float* sUm,
                                                   const float* sV, int t, int lane)
{
    u64t Fr0[8], Fr1[8];
#pragma unroll
    for (int k = 0; k < 8; k++) {
        float4 f = *(const float4*)(sFX + (t * 8 + k) * 128 + 4 * lane);
        Fr0[k] = pack2(f.x, f.y); Fr1[k] = pack2(f.z, f.w);
    }
    const float4 bq = *(const float4*)(sV + 128 + 4 * lane);
    const float4 gq = *(const float4*)(sV + 384 + 4 * lane);
    const float4 eq = *(const float4*)(sV + 512 + 4 * lane);
    const u64t b01 = pack2(bq.x, bq.y), b23 = pack2(bq.z, bq.w);

    u64t X20[8], X21[8];
#pragma unroll
    for (int k = 0; k < 8; k++) { X20[k] = 0ull; X21[k] = 0ull; }

#pragma unroll 4
    for (int n = 0; n < 64; n++) {
        float4 u0 = *(const float4*)(sUm + n * 8);
        float4 u1 = *(const float4*)(sUm + n * 8 + 4);
        u64t uk[8] = {dup2(u0.x), dup2(u0.y), dup2(u0.z), dup2(u0.w),
                      dup2(u1.x), dup2(u1.y), dup2(u1.z), dup2(u1.w)};
        u64t o0 = b01, o1 = b23;
#pragma unroll
        for (int k = 0; k < 8; k++) { fma2(o0, uk[k], Fr0[k]); fma2(o1, uk[k], Fr1[k]); }
        float a, b, c, d;
        unpack2(o0, a, b); unpack2(o1, c, d);
        float s = a + b + c + d;
        float s2 = a * a + b * b + c * c + d * d;
#pragma unroll
        for (int m = 1; m < 32; m <<= 1) {
            s  += __shfl_xor_sync(0xffffffffu, s, m);
            s2 += __shfl_xor_sync(0xffffffffu, s2, m);
        }
        const float mu = s * 0.0078125f;
        const float rstd = rsqrtf(s2 * 0.0078125f - mu * mu + 1e-5f);
        u64t hA = pack2(fmaxf((a - mu) * rstd * gq.x + eq.x, 0.f),
                        fmaxf((b - mu) * rstd * gq.y + eq.y, 0.f));
        u64t hB = pack2(fmaxf((c - mu) * rstd * gq.z + eq.z, 0.f),
                        fmaxf((d - mu) * rstd * gq.w + eq.w, 0.f));
#pragma unroll
        for (int k = 0; k < 8; k++) { fma2(X20[k], uk[k], hA); fma2(X21[k], uk[k], hB); }
    }
#pragma unroll
    for (int k = 0; k < 8; k++) {
        float a, b, c, d;
        unpack2(X20[k], a, b); unpack2(X21[k], c, d);
        *(float4*)(sFX + (t * 8 + k) * 128 + 4 * lane) = make_float4(a, b, c, d);
    }
}

// Stage E (v12 verbatim).
static __device__ __forceinline__ void tile_stageE(const float* sFX, const float* sUm,
                                                   const float* sV, const u64t* sWoB,
                                                   float* __restrict__ outg,
                                                   int t, int lane)
{
    u64t Fr0[8], Fr1[8];
#pragma unroll
    for (int k = 0; k < 8; k++) {
        float4 f = *(const float4*)(sFX + (t * 8 + k) * 128 + 4 * lane);
        Fr0[k] = pack2(f.x, f.y); Fr1[k] = pack2(f.z, f.w);
    }
    const float4 bq = *(const float4*)(sV + 256 + 4 * lane);
    const float4 gq = *(const float4*)(sV + 640 + 4 * lane);
    const float4 eq = *(const float4*)(sV + 768 + 4 * lane);
    const u64t b01 = pack2(bq.x, bq.y), b23 = pack2(bq.z, bq.w);

    u64t w2[4][4];
    {
        const int l7 = lane & 7;
#pragma unroll
        for (int u = 0; u < 8; u++) {
            int p = lane * 8 + (u ^ l7);
            u64t A = sWoB[2 * p], B = sWoB[2 * p + 1];
            const int j = u >> 1, qb = (u & 1) * 2;
            w2[j][qb] = A; w2[j][qb + 1] = B;
        }
    }
    const int g = lane >> 3;
    float2 boP = *(const float2*)(sV + 896 + 2 * g);

#pragma unroll 2
    for (int n = 0; n < 64; n++) {
        float4 u0 = *(const float4*)(sUm + n * 8);
        float4 u1 = *(const float4*)(sUm + n * 8 + 4);
        u64t uk[8] = {dup2(u0.x), dup2(u0.y), dup2(u0.z), dup2(u0.w),
                      dup2(u1.x), dup2(u1.y), dup2(u1.z), dup2(u1.w)};
        u64t o0 = b01, o1 = b23;
#pragma unroll
        for (int k = 0; k < 8; k++) { fma2(o0, uk[k], Fr0[k]); fma2(o1, uk[k], Fr1[k]); }
        float a, b, c, d;
        unpack2(o0, a, b); unpack2(o1, c, d);
        float s = a + b + c + d;
        float s2 = a * a + b * b + c * c + d * d;
#pragma unroll
        for (int m = 1; m < 32; m <<= 1) {
            s  += __shfl_xor_sync(0xffffffffu, s, m);
            s2 += __shfl_xor_sync(0xffffffffu, s2, m);
        }
        const float mu = s * 0.0078125f;
        const float rstd = rsqrtf(s2 * 0.0078125f - mu * mu + 1e-5f);
        float h0 = fmaxf((a - mu) * rstd * gq.x + eq.x, 0.f);
        float h1 = fmaxf((b - mu) * rstd * gq.y + eq.y, 0.f);
        float h2 = fmaxf((c - mu) * rstd * gq.z + eq.z, 0.f);
        float h3 = fmaxf((d - mu) * rstd * gq.w + eq.w, 0.f);

        u64t acc2[4] = {0ull, 0ull, 0ull, 0ull};
        u64t hb;
        hb = dup2(h0);
#pragma unroll
        for (int q = 0; q < 4; q++) fma2(acc2[q], hb, w2[0][q]);
        hb = dup2(h1);
#pragma unroll
        for (int q = 0; q < 4; q++) fma2(acc2[q], hb, w2[1][q]);
        hb = dup2(h2);
#pragma unroll
        for (int q = 0; q < 4; q++) fma2(acc2[q], hb, w2[2][q]);
        hb = dup2(h3);
#pragma unroll
        for (int q = 0; q < 4; q++) fma2(acc2[q], hb, w2[3][q]);

#pragma unroll
        for (int q = 0; q < 4; q++)
            acc2[q] = add2(acc2[q], __shfl_xor_sync(0xffffffffu, acc2[q], 16));
#pragma unroll
        for (int q = 0; q < 4; q++)
            acc2[q] = add2(acc2[q], __shfl_xor_sync(0xffffffffu, acc2[q], 8));
        u64t v = (g == 0) ? acc2[0] : (g == 1) ? acc2[1] : (g == 2) ? acc2[2] : acc2[3];
        v = add2(v, __shfl_xor_sync(0xffffffffu, v, 4));
        v = add2(v, __shfl_xor_sync(0xffffffffu, v, 2));
        v = add2(v, __shfl_xor_sync(0xffffffffu, v, 1));
        if ((lane & 7) == (n & 7)) {
            float x, y; unpack2(v, x, y);
            *(float2*)(outg + n * 8 + 2 * g) = make_float2(x + boP.x, y + boP.y);
        }
    }
}

__global__ void __launch_bounds__(NT, 2)
main_kernel(const float* __restrict__ x, const float* __restrict__ U,
            const float* __restrict__ Wp, const float* __restrict__ bp,
            const float* __restrict__ g1, const float* __restrict__ be1,
            const float* __restrict__ g3, const float* __restrict__ be3,
            const float* __restrict__ Wo, const float* __restrict__ bo,
            float* __restrict__ out)
{
    extern __shared__ float sm[];
    float* sFX  = sm + O_FX;
    float* sUm  = sm + O_UM;
    float* sWp  = sm + O_WP;
    float* sV   = sm + O_V;
    float* sY   = sm + O_Y;
    u64t*  sWoB = (u64t*)(sm + O_WOB);

    const int tid = threadIdx.x;
    const int wid = tid >> 5, lane = tid & 31;

    // ---- init: weights/vectors ----
    if (tid < 64) {
#pragma unroll
        for (int k = 0; k < 8; k++) sUm[tid * 8 + k] = U[tid * 64 + k];
    }
    for (int i = tid; i < 1024; i += NT) sWp[i] = Wp[i];
    if (tid < 128) {
        sV[tid]       = bp[tid];
        sV[128 + tid] = d_b1[tid];
        sV[256 + tid] = d_b3[tid];
        sV[384 + tid] = g1[tid];
        sV[512 + tid] = be1[tid];
        sV[640 + tid] = g3[tid];
        sV[768 + tid] = be3[tid];
    }
    if (tid < 8) { sV[896 + tid] = bo[tid]; sV[904 + tid] = d_tv[tid]; }
    if (tid < 256) {
        const int l = tid >> 3, u = (tid & 7) ^ (l & 7);
        const int j = u >> 1, qb = (u & 1) * 2;
        const int c = 4 * l + j;
        sWoB[2 * tid]     = pack2(Wo[c * 8 + 2 * qb],     Wo[c * 8 + 2 * qb + 1]);
        sWoB[2 * tid + 1] = pack2(Wo[c * 8 + 2 * qb + 2], Wo[c * 8 + 2 * qb + 3]);
    }
    __syncthreads();

    // ---- stage A pass 1: y[t][k][p] = sum_n Um[n,k] x[t][n][p] ----
    {
        const int k = lane >> 2, q = lane & 3;
        const float2* xg2 = (const float2*)(x + (size_t)blockIdx.x * 4096 + wid * 512);
        u64t acc = 0ull;
#pragma unroll 4
        for (int n = 0; n < 64; n++) {
            float um = sUm[n * 8 + k];
            float2 xv = __ldg(&xg2[n * 4 + q]);
            fma2(acc, dup2(um), pack2(xv.x, xv.y));
        }
        float a, b; unpack2(acc, a, b);
        *(float2*)(sY + wid * 64 + k * 8 + 2 * q) = make_float2(a, b);
    }
    __syncthreads();

    // ---- stage A pass 2: XF[t][k][c] = tv[k]*bp[c] + sum_p y[t][k][p] Wp[p][c] ----
    {
        const int k = wid, c4 = lane;
        const float tvk = sV[904 + k];
        const float4 bp4 = ((const float4*)sV)[c4];
#pragma unroll
        for (int t = 0; t < TT; t++) {
            const float* yv = sY + t * 64 + k * 8;
            u64t a01 = 0ull, a23 = 0ull;
            u64t tb = dup2(tvk);
            fma2(a01, tb, pack2(bp4.x, bp4.y));
            fma2(a23, tb, pack2(bp4.z, bp4.w));
#pragma unroll
            for (int p = 0; p < 8; p++) {
                u64t yb = dup2(yv[p]);
                float4 wp = ((const float4*)(sWp + p * 128))[c4];
                fma2(a01, yb, pack2(wp.x, wp.y));
                fma2(a23, yb, pack2(wp.z, wp.w));
            }
            float a, b, c, d;
            unpack2(a01, a, b); unpack2(a23, c, d);
            *(float4*)(sFX + (t * 8 + k) * 128 + 4 * c4) = make_float4(a, b, c, d);
        }
    }

    // ---- stage B: f0 via tensor cores (in place) ----
    mode_gemm(d_MA0h, d_MA0l, sFX, tid);
    __syncthreads();

    // ---- stage C ----
    tile_stageC(sFX, sUm, sV, wid, lane);
    __syncthreads();

    // ---- stage D: f2 via tensor cores (in place) ----
    mode_gemm(d_MA2h, d_MA2l, sFX, tid);
    __syncthreads();

    // ---- stage E ----
    float* outg = out + (size_t)blockIdx.x * 4096;
    tile_stageE(sFX, sUm, sV, sWoB, outg + wid * 512, wid, lane);
}

// ------------------------------- launch ------------------------------------

extern "C" void kernel_launch(void* const* d_in, const int* in_sizes, int n_in,
                              void* d_out, int out_size)
{
    const float* x   = (const float*)d_in[0];
    const float* adj = (const float*)d_in[1];
    const float* U   = (const float*)d_in[2];
    const float* Wp  = (const float*)d_in[3];
    const float* bp  = (const float*)d_in[4];
    const float* w0  = (const float*)d_in[5];
    const float* w2  = (const float*)d_in[6];
    const float* Ws1 = (const float*)d_in[7];
    const float* bs1 = (const float*)d_in[8];
    const float* Wn1 = (const float*)d_in[9];
    const float* bn1 = (const float*)d_in[10];
    const float* g1  = (const float*)d_in[11];
    const float* be1 = (const float*)d_in[12];
    const float* Ws3 = (const float*)d_in[13];
    const float* bs3 = (const float*)d_in[14];
    const float* Wn3 = (const float*)d_in[15];
    const float* bn3 = (const float*)d_in[16];
    const float* g3  = (const float*)d_in[17];
    const float* be3 = (const float*)d_in[18];
    const float* Wo  = (const float*)d_in[19];
    const float* bo  = (const float*)d_in[20];
    float* out = (float*)d_out;

    pre_kernel<<<256, 128>>>(U, adj, w0, w2, Ws1, Wn1, Ws3, Wn3,
                             bs1, bn1, bs3, bn3);

    const size_t smem = SMEMF * sizeof(float);  // 48 KB -> 2 CTAs/SM
    cudaFuncSetAttribute(main_kernel, cudaFuncAttributeMaxDynamicSharedMemorySize,
                         (int)smem);
    main_kernel<<<2048, NT, smem>>>(x, U, Wp, bp, g1, be1, g3, be3, Wo, bo, out);
}

// round 16
// speedup vs baseline: 1.0254x; 1.0254x over previous
#include <cuda_runtime.h>

// ---------------------------------------------------------------------------
// Model_19095424598065 v16 : algebraically reduced graph-spectral net.
// vs v15 (tf32 MMA, correct but 687us): (1) dual independent accumulator
// chains (cblk pairs) halve the exposed MMA latency; (2) M stored fp32 in
// a-fragment order (1 MB/CTA traffic, same as fp32 path) with in-kernel
// hi/lo tf32 split for 3xTF32 accuracy. Stages A/C/E = v12 verbatim.
// ---------------------------------------------------------------------------

typedef unsigned long long u64t;
typedef unsigned int u32t;

#define NT 256
#define TT 8

// fp32 M in a-fragment order: [k][cblk][kblk][lane][slot]
__device__ float d_MA0[8 * 8 * 16 * 32 * 4];
__device__ float d_MA2[8 * 8 * 16 * 32 * 4];
__device__ float d_tv[8];
__device__ float d_b1[128];
__device__ float d_b3[128];

// ------------------------------ helpers ------------------------------------
static __device__ __forceinline__ u64t dup2(float x) {
    u64t r; asm("mov.b64 %0, {%1, %1};" : "=l"(r) : "f"(x)); return r;
}
static __device__ __forceinline__ u64t pack2(float a, float b) {
    u64t r; asm("mov.b64 %0, {%1, %2};" : "=l"(r) : "f"(a), "f"(b)); return r;
}
static __device__ __forceinline__ void unpack2(u64t v, float& a, float& b) {
    asm("mov.b64 {%0, %1}, %2;" : "=f"(a), "=f"(b) : "l"(v));
}
static __device__ __forceinline__ void fma2(u64t& d, u64t a, u64t b) {
    asm("fma.rn.f32x2 %0, %1, %2, %3;" : "=l"(d) : "l"(a), "l"(b), "l"(d));
}
static __device__ __forceinline__ u64t add2(u64t a, u64t b) {
    u64t r; asm("add.rn.f32x2 %0, %1, %2;" : "=l"(r) : "l"(a), "l"(b)); return r;
}
static __device__ __forceinline__ u32t to_tf32(float f) {
    u32t u; asm("cvt.rna.tf32.f32 %0, %1;" : "=r"(u) : "f"(f)); return u;
}
static __device__ __forceinline__ void mma_tf32(float& c0, float& c1,
                                                float& c2, float& c3,
                                                u32t a0, u32t a1, u32t a2, u32t a3,
                                                u32t b0, u32t b1) {
    asm volatile(
        "mma.sync.aligned.m16n8k8.row.col.f32.tf32.tf32.f32 "
        "{%0,%1,%2,%3}, {%4,%5,%6,%7}, {%8,%9}, {%0,%1,%2,%3};"
        : "+f"(c0), "+f"(c1), "+f"(c2), "+f"(c3)
        : "r"(a0), "r"(a1), "r"(a2), "r"(a3), "r"(b0), "r"(b1));
}

// --------------------------- fused precompute ------------------------------
// 256 blocks: b<128 -> stage0 K-row b; b>=128 -> stage2 K-row b-128.
// M_k[i][c] scattered fp32 into a-fragment order for A = M_k^T.
__global__ void pre_kernel(const float* __restrict__ U, const float* __restrict__ adj,
                           const float* __restrict__ w0, const float* __restrict__ w2,
                           const float* __restrict__ Ws1, const float* __restrict__ Wn1,
                           const float* __restrict__ Ws3, const float* __restrict__ Wn3,
                           const float* __restrict__ bs1, const float* __restrict__ bn1,
                           const float* __restrict__ bs3, const float* __restrict__ bn3)
{
    __shared__ float sw[1024];
    __shared__ float spart[128];
    __shared__ float slam[8];
    const int b = blockIdx.x, c = threadIdx.x;
    const int which = b >> 7, i = b & 127;
    const float* w  = which ? w2  : w0;
    const float* Ws = which ? Ws3 : Ws1;
    const float* Wn = which ? Wn3 : Wn1;

    {
        const int k = c >> 4, s = c & 15;
        float part = 0.f;
        for (int n = s; n < 64; n += 16) {
            float g = 0.f;
            for (int m = 0; m < 64; m++) g += adj[n * 64 + m] * U[m * 64 + k];
            part += U[n * 64 + k] * g;
        }
        spart[c] = part;
    }
    for (int idx = c; idx < 1024; idx += 128) sw[idx] = w[i * 1024 + idx];
    __syncthreads();
    if (c < 8) {
        float lam = 0.f;
        for (int s = 0; s < 16; s++) lam += spart[c * 16 + s];
        slam[c] = lam;
    }
    if (b == 0) {
        if (c < 128) { d_b1[c] = bs1[c] + bn1[c]; d_b3[c] = bs3[c] + bn3[c]; }
        if (c < 8) {
            float ts = 0.f;
            for (int n = 0; n < 64; n++) ts += U[n * 64 + c];
            d_tv[c] = ts;
        }
    }
    __syncthreads();

    float lam[8], acc[8];
#pragma unroll
    for (int k = 0; k < 8; k++) { lam[k] = slam[k]; acc[k] = 0.f; }
#pragma unroll 2
    for (int j = 0; j < 128; j++) {
        float ws = __ldg(Ws + j * 128 + c);
        float wn = __ldg(Wn + j * 128 + c);
#pragma unroll
        for (int k = 0; k < 8; k++)
            acc[k] += sw[j * 8 + k] * fmaf(lam[k], wn, ws);
    }
    // Fragment scatter (validated in R15): value M_k[i][c] = A element (c,i)
    float* MA = which ? d_MA2 : d_MA0;
    const int cblk = c >> 4, c_r = c & 15, kblk = i >> 3, i_r = i & 7;
    const int g = c_r & 7, half = c_r >> 3;
    const int slot = half + 2 * (i_r >> 2);
    const int lane = g * 4 + (i_r & 3);
#pragma unroll
    for (int k = 0; k < 8; k++) {
        const int idx = (((k * 8 + cblk) * 16 + kblk) * 32 + lane) * 4 + slot;
        MA[idx] = acc[k];
    }
}

// ------------------------------- main kernel -------------------------------
// smem (floats): identical to v12.
#define O_FX  0
#define O_UM  8192
#define O_WP  8704
#define O_V   9728
#define O_Y   10752
#define O_WOB 11264
#define SMEMF 12288

// mode_gemm via tensor cores, dual-chain. Warp k owns mode k.
// F^T[c][t] = sum_i M_k^T[c][i] * XF_k[t][i], m16n8k8 3xTF32, hi/lo split
// of A computed in-kernel from fp32 fragments (halves M traffic vs v15).
static __device__ __forceinline__ void mode_gemm(const float* __restrict__ MF,
                                                 float* sFX, int tid)
{
    const int k = tid >> 5, lane = tid & 31;
    const int g = lane >> 2, tig = lane & 3;

    // ---- preload B fragments (XF^T) hi/lo; in-place stores become safe ----
    u32t bh[32], bl[32];
    {
        const float* xb = sFX + (g * 8 + k) * 128 + tig;
#pragma unroll
        for (int kb = 0; kb < 16; kb++) {
            float v0 = xb[kb * 8];
            float v1 = xb[kb * 8 + 4];
            u32t h0 = to_tf32(v0), h1 = to_tf32(v1);
            bh[2 * kb] = h0; bh[2 * kb + 1] = h1;
            bl[2 * kb]     = to_tf32(v0 - __uint_as_float(h0));
            bl[2 * kb + 1] = to_tf32(v1 - __uint_as_float(h1));
        }
    }

    const float4* MA = (const float4*)MF + (k * 8) * 16 * 32;

#pragma unroll 1
    for (int cp = 0; cp < 4; cp++) {
        float c00 = 0.f, c01 = 0.f, c02 = 0.f, c03 = 0.f;   // cblk = 2cp
        float c10 = 0.f, c11 = 0.f, c12 = 0.f, c13 = 0.f;   // cblk = 2cp+1
        const float4* A0 = MA + (2 * cp)     * 16 * 32 + lane;
        const float4* A1 = MA + (2 * cp + 1) * 16 * 32 + lane;
#pragma unroll 4
        for (int kb = 0; kb < 16; kb++) {
            float4 a0 = __ldg(A0 + kb * 32);
            float4 a1 = __ldg(A1 + kb * 32);
            u32t h0x = to_tf32(a0.x), h0y = to_tf32(a0.y),
                 h0z = to_tf32(a0.z), h0w = to_tf32(a0.w);
            u32t l0x = to_tf32(a0.x - __uint_as_float(h0x)),
                 l0y = to_tf32(a0.y - __uint_as_float(h0y)),
                 l0z = to_tf32(a0.z - __uint_as_float(h0z)),
                 l0w = to_tf32(a0.w - __uint_as_float(h0w));
            u32t h1x = to_tf32(a1.x), h1y = to_tf32(a1.y),
                 h1z = to_tf32(a1.z), h1w = to_tf32(a1.w);
            u32t l1x = to_tf32(a1.x - __uint_as_float(h1x)),
                 l1y = to_tf32(a1.y - __uint_as_float(h1y)),
                 l1z = to_tf32(a1.z - __uint_as_float(h1z)),
                 l1w = to_tf32(a1.w - __uint_as_float(h1w));
            const u32t b0 = bh[2 * kb], b1 = bh[2 * kb + 1];
            const u32t e0 = bl[2 * kb], e1 = bl[2 * kb + 1];
            // two independent chains, interleaved issue
            mma_tf32(c00, c01, c02, c03, h0x, h0y, h0z, h0w, b0, b1);
            mma_tf32(c10, c11, c12, c13, h1x, h1y, h1z, h1w, b0, b1);
            mma_tf32(c00, c01, c02, c03, h0x, h0y, h0z, h0w, e0, e1);
            mma_tf32(c10, c11, c12, c13, h1x, h1y, h1z, h1w, e0, e1);
            mma_tf32(c00, c01, c02, c03, l0x, l0y, l0z, l0w, b0, b1);
            mma_tf32(c10, c11, c12, c13, l1x, l1y, l1z, l1w, b0, b1);
        }
        // c-frag mapping (validated in R15):
        // c0:(row=g,col=2tig) c1:(g,2tig+1) c2:(g+8,2tig) c3:(g+8,2tig+1)
        {
            const int cl0 = (2 * cp) * 16 + g;
            sFX[((2 * tig)     * 8 + k) * 128 + cl0]     = c00;
            sFX[((2 * tig + 1) * 8 + k) * 128 + cl0]     = c01;
            sFX[((2 * tig)     * 8 + k) * 128 + cl0 + 8] = c02;
            sFX[((2 * tig + 1) * 8 + k) * 128 + cl0 + 8] = c03;
            const int cl1 = (2 * cp + 1) * 16 + g;
            sFX[((2 * tig)     * 8 + k) * 128 + cl1]     = c10;
            sFX[((2 * tig + 1) * 8 + k) * 128 + cl1]     = c11;
            sFX[((2 * tig)     * 8 + k) * 128 + cl1 + 8] = c12;
            sFX[((2 * tig + 1) * 8 + k) * 128 + cl1 + 8] = c13;
        }
    }
}

// Stage C (v12 verbatim).
static __device__ __forceinline__ void tile_stageC(float* sFX, const float* sUm,
                                                   const float* sV, int t, int lane)
{
    u64t Fr0[8], Fr1[8];
#pragma unroll
    for (int k = 0; k < 8; k++) {
        float4 f = *(const float4*)(sFX + (t * 8 + k) * 128 + 4 * lane);
        Fr0[k] = pack2(f.x, f.y); Fr1[k] = pack2(f.z, f.w);
    }
    const float4 bq = *(const float4*)(sV + 128 + 4 * lane);
    const float4 gq = *(const float4*)(sV + 384 + 4 * lane);
    const float4 eq = *(const float4*)(sV + 512 + 4 * lane);
    const u64t b01 = pack2(bq.x, bq.y), b23 = pack2(bq.z, bq.w);

    u64t X20[8], X21[8];
#pragma unroll
    for (int k = 0; k < 8; k++) { X20[k] = 0ull; X21[k] = 0ull; }

#pragma unroll 4
    for (int n = 0; n < 64; n++) {
        float4 u0 = *(const float4*)(sUm + n * 8);
        float4 u1 = *(const float4*)(sUm + n * 8 + 4);
        u64t uk[8] = {dup2(u0.x), dup2(u0.y), dup2(u0.z), dup2(u0.w),
                      dup2(u1.x), dup2(u1.y), dup2(u1.z), dup2(u1.w)};
        u64t o0 = b01, o1 = b23;
#pragma unroll
        for (int k = 0; k < 8; k++) { fma2(o0, uk[k], Fr0[k]); fma2(o1, uk[k], Fr1[k]); }
        float a, b, c, d;
        unpack2(o0, a, b); unpack2(o1, c, d);
        float s = a + b + c + d;
        float s2 = a * a + b * b + c * c + d * d;
#pragma unroll
        for (int m = 1; m < 32; m <<= 1) {
            s  += __shfl_xor_sync(0xffffffffu, s, m);
            s2 += __shfl_xor_sync(0xffffffffu, s2, m);
        }
        const float mu = s * 0.0078125f;
        const float rstd = rsqrtf(s2 * 0.0078125f - mu * mu + 1e-5f);
        u64t hA = pack2(fmaxf((a - mu) * rstd * gq.x + eq.x, 0.f),
                        fmaxf((b - mu) * rstd * gq.y + eq.y, 0.f));
        u64t hB = pack2(fmaxf((c - mu) * rstd * gq.z + eq.z, 0.f),
                        fmaxf((d - mu) * rstd * gq.w + eq.w, 0.f));
#pragma unroll
        for (int k = 0; k < 8; k++) { fma2(X20[k], uk[k], hA); fma2(X21[k], uk[k], hB); }
    }
#pragma unroll
    for (int k = 0; k < 8; k++) {
        float a, b, c, d;
        unpack2(X20[k], a, b); unpack2(X21[k], c, d);
        *(float4*)(sFX + (t * 8 + k) * 128 + 4 * lane) = make_float4(a, b, c, d);
    }
}

// Stage E (v12 verbatim).
static __device__ __forceinline__ void tile_stageE(const float* sFX, const float* sUm,
                                                   const float* sV, const u64t* sWoB,
                                                   float* __restrict__ outg,
                                                   int t, int lane)
{
    u64t Fr0[8], Fr1[8];
#pragma unroll
    for (int k = 0; k < 8; k++) {
        float4 f = *(const float4*)(sFX + (t * 8 + k) * 128 + 4 * lane);
        Fr0[k] = pack2(f.x, f.y); Fr1[k] = pack2(f.z, f.w);
    }
    const float4 bq = *(const float4*)(sV + 256 + 4 * lane);
    const float4 gq = *(const float4*)(sV + 640 + 4 * lane);
    const float4 eq = *(const float4*)(sV + 768 + 4 * lane);
    const u64t b01 = pack2(bq.x, bq.y), b23 = pack2(bq.z, bq.w);

    u64t w2[4][4];
    {
        const int l7 = lane & 7;
#pragma unroll
        for (int u = 0; u < 8; u++) {
            int p = lane * 8 + (u ^ l7);
            u64t A = sWoB[2 * p], B = sWoB[2 * p + 1];
            const int j = u >> 1, qb = (u & 1) * 2;
            w2[j][qb] = A; w2[j][qb + 1] = B;
        }
    }
    const int g = lane >> 3;
    float2 boP = *(const float2*)(sV + 896 + 2 * g);

#pragma unroll 2
    for (int n = 0; n < 64; n++) {
        float4 u0 = *(const float4*)(sUm + n * 8);
        float4 u1 = *(const float4*)(sUm + n * 8 + 4);
        u64t uk[8] = {dup2(u0.x), dup2(u0.y), dup2(u0.z), dup2(u0.w),
                      dup2(u1.x), dup2(u1.y), dup2(u1.z), dup2(u1.w)};
        u64t o0 = b01, o1 = b23;
#pragma unroll
        for (int k = 0; k < 8; k++) { fma2(o0, uk[k], Fr0[k]); fma2(o1, uk[k], Fr1[k]); }
        float a, b, c, d;
        unpack2(o0, a, b); unpack2(o1, c, d);
        float s = a + b + c + d;
        float s2 = a * a + b * b + c * c + d * d;
#pragma unroll
        for (int m = 1; m < 32; m <<= 1) {
            s  += __shfl_xor_sync(0xffffffffu, s, m);
            s2 += __shfl_xor_sync(0xffffffffu, s2, m);
        }
        const float mu = s * 0.0078125f;
        const float rstd = rsqrtf(s2 * 0.0078125f - mu * mu + 1e-5f);
        float h0 = fmaxf((a - mu) * rstd * gq.x + eq.x, 0.f);
        float h1 = fmaxf((b - mu) * rstd * gq.y + eq.y, 0.f);
        float h2 = fmaxf((c - mu) * rstd * gq.z + eq.z, 0.f);
        float h3 = fmaxf((d - mu) * rstd * gq.w + eq.w, 0.f);

        u64t acc2[4] = {0ull, 0ull, 0ull, 0ull};
        u64t hb;
        hb = dup2(h0);
#pragma unroll
        for (int q = 0; q < 4; q++) fma2(acc2[q], hb, w2[0][q]);
        hb = dup2(h1);
#pragma unroll
        for (int q = 0; q < 4; q++) fma2(acc2[q], hb, w2[1][q]);
        hb = dup2(h2);
#pragma unroll
        for (int q = 0; q < 4; q++) fma2(acc2[q], hb, w2[2][q]);
        hb = dup2(h3);
#pragma unroll
        for (int q = 0; q < 4; q++) fma2(acc2[q], hb, w2[3][q]);

#pragma unroll
        for (int q = 0; q < 4; q++)
            acc2[q] = add2(acc2[q], __shfl_xor_sync(0xffffffffu, acc2[q], 16));
#pragma unroll
        for (int q = 0; q < 4; q++)
            acc2[q] = add2(acc2[q], __shfl_xor_sync(0xffffffffu, acc2[q], 8));
        u64t v = (g == 0) ? acc2[0] : (g == 1) ? acc2[1] : (g == 2) ? acc2[2] : acc2[3];
        v = add2(v, __shfl_xor_sync(0xffffffffu, v, 4));
        v = add2(v, __shfl_xor_sync(0xffffffffu, v, 2));
        v = add2(v, __shfl_xor_sync(0xffffffffu, v, 1));
        if ((lane & 7) == (n & 7)) {
            float x, y; unpack2(v, x, y);
            *(float2*)(outg + n * 8 + 2 * g) = make_float2(x + boP.x, y + boP.y);
        }
    }
}

__global__ void __launch_bounds__(NT, 2)
main_kernel(const float* __restrict__ x, const float* __restrict__ U,
            const float* __restrict__ Wp, const float* __restrict__ bp,
            const float* __restrict__ g1, const float* __restrict__ be1,
            const float* __restrict__ g3, const float* __restrict__ be3,
            const float* __restrict__ Wo, const float* __restrict__ bo,
            float* __restrict__ out)
{
    extern __shared__ float sm[];
    float* sFX  = sm + O_FX;
    float* sUm  = sm + O_UM;
    float* sWp  = sm + O_WP;
    float* sV   = sm + O_V;
    float* sY   = sm + O_Y;
    u64t*  sWoB = (u64t*)(sm + O_WOB);

    const int tid = threadIdx.x;
    const int wid = tid >> 5, lane = tid & 31;

    // ---- init: weights/vectors ----
    if (tid < 64) {
#pragma unroll
        for (int k = 0; k < 8; k++) sUm[tid * 8 + k] = U[tid * 64 + k];
    }
    for (int i = tid; i < 1024; i += NT) sWp[i] = Wp[i];
    if (tid < 128) {
        sV[tid]       = bp[tid];
        sV[128 + tid] = d_b1[tid];
        sV[256 + tid] = d_b3[tid];
        sV[384 + tid] = g1[tid];
        sV[512 + tid] = be1[tid];
        sV[640 + tid] = g3[tid];
        sV[768 + tid] = be3[tid];
    }
    if (tid < 8) { sV[896 + tid] = bo[tid]; sV[904 + tid] = d_tv[tid]; }
    if (tid < 256) {
        const int l = tid >> 3, u = (tid & 7) ^ (l & 7);
        const int j = u >> 1, qb = (u & 1) * 2;
        const int c = 4 * l + j;
        sWoB[2 * tid]     = pack2(Wo[c * 8 + 2 * qb],     Wo[c * 8 + 2 * qb + 1]);
        sWoB[2 * tid + 1] = pack2(Wo[c * 8 + 2 * qb + 2], Wo[c * 8 + 2 * qb + 3]);
    }
    __syncthreads();

    // ---- stage A pass 1: y[t][k][p] = sum_n Um[n,k] x[t][n][p] ----
    {
        const int k = lane >> 2, q = lane & 3;
        const float2* xg2 = (const float2*)(x + (size_t)blockIdx.x * 4096 + wid * 512);
        u64t acc = 0ull;
#pragma unroll 4
        for (int n = 0; n < 64; n++) {
            float um = sUm[n * 8 + k];
            float2 xv = __ldg(&xg2[n * 4 + q]);
            fma2(acc, dup2(um), pack2(xv.x, xv.y));
        }
        float a, b; unpack2(acc, a, b);
        *(float2*)(sY + wid * 64 + k * 8 + 2 * q) = make_float2(a, b);
    }
    __syncthreads();

    // ---- stage A pass 2: XF[t][k][c] = tv[k]*bp[c] + sum_p y[t][k][p] Wp[p][c] ----
    {
        const int k = wid, c4 = lane;
        const float tvk = sV[904 + k];
        const float4 bp4 = ((const float4*)sV)[c4];
#pragma unroll
        for (int t = 0; t < TT; t++) {
            const float* yv = sY + t * 64 + k * 8;
            u64t a01 = 0ull, a23 = 0ull;
            u64t tb = dup2(tvk);
            fma2(a01, tb, pack2(bp4.x, bp4.y));
            fma2(a23, tb, pack2(bp4.z, bp4.w));
#pragma unroll
            for (int p = 0; p < 8; p++) {
                u64t yb = dup2(yv[p]);
                float4 wp = ((const float4*)(sWp + p * 128))[c4];
                fma2(a01, yb, pack2(wp.x, wp.y));
                fma2(a23, yb, pack2(wp.z, wp.w));
            }
            float a, b, c, d;
            unpack2(a01, a, b); unpack2(a23, c, d);
            *(float4*)(sFX + (t * 8 + k) * 128 + 4 * c4) = make_float4(a, b, c, d);
        }
    }

    // ---- stage B: f0 via tensor cores (in place) ----
    mode_gemm(d_MA0, sFX, tid);
    __syncthreads();

    // ---- stage C ----
    tile_stageC(sFX, sUm, sV, wid, lane);
    __syncthreads();

    // ---- stage D: f2 via tensor cores (in place) ----
    mode_gemm(d_MA2, sFX, tid);
    __syncthreads();

    // ---- stage E ----
    float* outg = out + (size_t)blockIdx.x * 4096;
    tile_stageE(sFX, sUm, sV, sWoB, outg + wid * 512, wid, lane);
}

// ------------------------------- launch ------------------------------------

extern "C" void kernel_launch(void* const* d_in, const int* in_sizes, int n_in,
                              void* d_out, int out_size)
{
    const float* x   = (const float*)d_in[0];
    const float* adj = (const float*)d_in[1];
    const float* U   = (const float*)d_in[2];
    const float* Wp  = (const float*)d_in[3];
    const float* bp  = (const float*)d_in[4];
    const float* w0  = (const float*)d_in[5];
    const float* w2  = (const float*)d_in[6];
    const float* Ws1 = (const float*)d_in[7];
    const float* bs1 = (const float*)d_in[8];
    const float* Wn1 = (const float*)d_in[9];
    const float* bn1 = (const float*)d_in[10];
    const float* g1  = (const float*)d_in[11];
    const float* be1 = (const float*)d_in[12];
    const float* Ws3 = (const float*)d_in[13];
    const float* bs3 = (const float*)d_in[14];
    const float* Wn3 = (const float*)d_in[15];
    const float* bn3 = (const float*)d_in[16];
    const float* g3  = (const float*)d_in[17];
    const float* be3 = (const float*)d_in[18];
    const float* Wo  = (const float*)d_in[19];
    const float* bo  = (const float*)d_in[20];
    float* out = (float*)d_out;

    pre_kernel<<<256, 128>>>(U, adj, w0, w2, Ws1, Wn1, Ws3, Wn3,
                             bs1, bn1, bs3, bn3);

    const size_t smem = SMEMF * sizeof(float);  // 48 KB -> 2 CTAs/SM
    cudaFuncSetAttribute(main_kernel, cudaFuncAttributeMaxDynamicSharedMemorySize,
                         (int)smem);
    main_kernel<<<2048, NT, smem>>>(x, U, Wp, bp, g1, be1, g3, be3, Wo, bo, out);
}

// round 17
// speedup vs baseline: 1.1025x; 1.0752x over previous
#include <cuda_runtime.h>

// ---------------------------------------------------------------------------
// Model_19095424598065 v17 : algebraically reduced graph-spectral net.
// tf32 tensor-core mode_gemm, third iteration:
//   - hi/lo tf32 fragments PRECOMPUTED (R15 layout; zero in-kernel CVT —
//     R16 measured the in-kernel split at +19% alu pipe)
//   - QUAD independent accumulator chains (4 cblks in flight) to cover the
//     ~16cyc MMA latency that serialized R15 (issue 41%).
// Stages A/C/E and pre_kernel math = v12 verbatim.
// ---------------------------------------------------------------------------

typedef unsigned long long u64t;
typedef unsigned int u32t;

#define NT 256
#define TT 8

// A-fragment-packed M (hi/lo tf32 bits): [k][cblk][kblk][lane][slot]
__device__ u32t d_MA0h[8 * 8 * 16 * 32 * 4];
__device__ u32t d_MA0l[8 * 8 * 16 * 32 * 4];
__device__ u32t d_MA2h[8 * 8 * 16 * 32 * 4];
__device__ u32t d_MA2l[8 * 8 * 16 * 32 * 4];
__device__ float d_tv[8];
__device__ float d_b1[128];
__device__ float d_b3[128];

// ------------------------------ helpers ------------------------------------
static __device__ __forceinline__ u64t dup2(float x) {
    u64t r; asm("mov.b64 %0, {%1, %1};" : "=l"(r) : "f"(x)); return r;
}
static __device__ __forceinline__ u64t pack2(float a, float b) {
    u64t r; asm("mov.b64 %0, {%1, %2};" : "=l"(r) : "f"(a), "f"(b)); return r;
}
static __device__ __forceinline__ void unpack2(u64t v, float& a, float& b) {
    asm("mov.b64 {%0, %1}, %2;" : "=f"(a), "=f"(b) : "l"(v));
}
static __device__ __forceinline__ void fma2(u64t& d, u64t a, u64t b) {
    asm("fma.rn.f32x2 %0, %1, %2, %3;" : "=l"(d) : "l"(a), "l"(b), "l"(d));
}
static __device__ __forceinline__ u64t add2(u64t a, u64t b) {
    u64t r; asm("add.rn.f32x2 %0, %1, %2;" : "=l"(r) : "l"(a), "l"(b)); return r;
}
static __device__ __forceinline__ u32t to_tf32(float f) {
    u32t u; asm("cvt.rna.tf32.f32 %0, %1;" : "=r"(u) : "f"(f)); return u;
}
static __device__ __forceinline__ void mma_tf32(float& c0, float& c1,
                                                float& c2, float& c3,
                                                u32t a0, u32t a1, u32t a2, u32t a3,
                                                u32t b0, u32t b1) {
    asm volatile(
        "mma.sync.aligned.m16n8k8.row.col.f32.tf32.tf32.f32 "
        "{%0,%1,%2,%3}, {%4,%5,%6,%7}, {%8,%9}, {%0,%1,%2,%3};"
        : "+f"(c0), "+f"(c1), "+f"(c2), "+f"(c3)
        : "r"(a0), "r"(a1), "r"(a2), "r"(a3), "r"(b0), "r"(b1));
}

// --------------------------- fused precompute ------------------------------
// 256 blocks: b<128 -> stage0 K-row b; b>=128 -> stage2 K-row b-128.
// M_k[i][c] scattered hi/lo tf32 into a-fragment order (validated in R15).
__global__ void pre_kernel(const float* __restrict__ U, const float* __restrict__ adj,
                           const float* __restrict__ w0, const float* __restrict__ w2,
                           const float* __restrict__ Ws1, const float* __restrict__ Wn1,
                           const float* __restrict__ Ws3, const float* __restrict__ Wn3,
                           const float* __restrict__ bs1, const float* __restrict__ bn1,
                           const float* __restrict__ bs3, const float* __restrict__ bn3)
{
    __shared__ float sw[1024];
    __shared__ float spart[128];
    __shared__ float slam[8];
    const int b = blockIdx.x, c = threadIdx.x;
    const int which = b >> 7, i = b & 127;
    const float* w  = which ? w2  : w0;
    const float* Ws = which ? Ws3 : Ws1;
    const float* Wn = which ? Wn3 : Wn1;

    {
        const int k = c >> 4, s = c & 15;
        float part = 0.f;
        for (int n = s; n < 64; n += 16) {
            float g = 0.f;
            for (int m = 0; m < 64; m++) g += adj[n * 64 + m] * U[m * 64 + k];
            part += U[n * 64 + k] * g;
        }
        spart[c] = part;
    }
    for (int idx = c; idx < 1024; idx += 128) sw[idx] = w[i * 1024 + idx];
    __syncthreads();
    if (c < 8) {
        float lam = 0.f;
        for (int s = 0; s < 16; s++) lam += spart[c * 16 + s];
        slam[c] = lam;
    }
    if (b == 0) {
        if (c < 128) { d_b1[c] = bs1[c] + bn1[c]; d_b3[c] = bs3[c] + bn3[c]; }
        if (c < 8) {
            float ts = 0.f;
            for (int n = 0; n < 64; n++) ts += U[n * 64 + c];
            d_tv[c] = ts;
        }
    }
    __syncthreads();

    float lam[8], acc[8];
#pragma unroll
    for (int k = 0; k < 8; k++) { lam[k] = slam[k]; acc[k] = 0.f; }
#pragma unroll 2
    for (int j = 0; j < 128; j++) {
        float ws = __ldg(Ws + j * 128 + c);
        float wn = __ldg(Wn + j * 128 + c);
#pragma unroll
        for (int k = 0; k < 8; k++)
            acc[k] += sw[j * 8 + k] * fmaf(lam[k], wn, ws);
    }
    u32t* MH = which ? d_MA2h : d_MA0h;
    u32t* ML = which ? d_MA2l : d_MA0l;
    const int cblk = c >> 4, c_r = c & 15, kblk = i >> 3, i_r = i & 7;
    const int g = c_r & 7, half = c_r >> 3;
    const int slot = half + 2 * (i_r >> 2);
    const int lane = g * 4 + (i_r & 3);
#pragma unroll
    for (int k = 0; k < 8; k++) {
        float v = acc[k];
        u32t hb = to_tf32(v);
        u32t lb = to_tf32(v - __uint_as_float(hb));
        const int idx = (((k * 8 + cblk) * 16 + kblk) * 32 + lane) * 4 + slot;
        MH[idx] = hb;
        ML[idx] = lb;
    }
}

// ------------------------------- main kernel -------------------------------
#define O_FX  0
#define O_UM  8192
#define O_WP  8704
#define O_V   9728
#define O_Y   10752
#define O_WOB 11264
#define SMEMF 12288

// mode_gemm via tensor cores, QUAD-chain. Warp k owns mode k.
// F^T[c][t] = sum_i M_k^T[c][i] * XF_k[t][i], m16n8k8 3xTF32,
// hi/lo precomputed, 4 independent cblk chains per pass (2 passes).
static __device__ __forceinline__ void mode_gemm(const u32t* __restrict__ MH,
                                                 const u32t* __restrict__ ML,
                                                 float* sFX, int tid)
{
    const int k = tid >> 5, lane = tid & 31;
    const int g = lane >> 2, tig = lane & 3;

    // ---- preload B fragments (XF^T) hi/lo; in-place stores become safe ----
    u32t bh[32], bl[32];
    {
        const float* xb = sFX + (g * 8 + k) * 128 + tig;
#pragma unroll
        for (int kb = 0; kb < 16; kb++) {
            float v0 = xb[kb * 8];
            float v1 = xb[kb * 8 + 4];
            u32t h0 = to_tf32(v0), h1 = to_tf32(v1);
            bh[2 * kb] = h0; bh[2 * kb + 1] = h1;
            bl[2 * kb]     = to_tf32(v0 - __uint_as_float(h0));
            bl[2 * kb + 1] = to_tf32(v1 - __uint_as_float(h1));
        }
    }

    const uint4* MAh = (const uint4*)MH + (k * 8) * 16 * 32;
    const uint4* MAl = (const uint4*)ML + (k * 8) * 16 * 32;

#pragma unroll 1
    for (int hh = 0; hh < 2; hh++) {
        float ac[4][4];
#pragma unroll
        for (int j = 0; j < 4; j++)
#pragma unroll
            for (int q = 0; q < 4; q++) ac[j][q] = 0.f;

#pragma unroll 2
        for (int kb = 0; kb < 16; kb++) {
            uint4 Ah[4], Al[4];
#pragma unroll
            for (int j = 0; j < 4; j++) {
                const int fo = ((4 * hh + j) * 16 + kb) * 32 + lane;
                Ah[j] = __ldg(&MAh[fo]);
                Al[j] = __ldg(&MAl[fo]);
            }
            const u32t b0 = bh[2 * kb], b1 = bh[2 * kb + 1];
            const u32t e0 = bl[2 * kb], e1 = bl[2 * kb + 1];
#pragma unroll
            for (int j = 0; j < 4; j++)
                mma_tf32(ac[j][0], ac[j][1], ac[j][2], ac[j][3],
                         Ah[j].x, Ah[j].y, Ah[j].z, Ah[j].w, b0, b1);
#pragma unroll
            for (int j = 0; j < 4; j++)
                mma_tf32(ac[j][0], ac[j][1], ac[j][2], ac[j][3],
                         Ah[j].x, Ah[j].y, Ah[j].z, Ah[j].w, e0, e1);
#pragma unroll
            for (int j = 0; j < 4; j++)
                mma_tf32(ac[j][0], ac[j][1], ac[j][2], ac[j][3],
                         Al[j].x, Al[j].y, Al[j].z, Al[j].w, b0, b1);
        }
        // c-frag mapping (validated in R15):
        // c0:(row=g,col=2tig) c1:(g,2tig+1) c2:(g+8,2tig) c3:(g+8,2tig+1)
#pragma unroll
        for (int j = 0; j < 4; j++) {
            const int cl = (4 * hh + j) * 16 + g;
            sFX[((2 * tig)     * 8 + k) * 128 + cl]     = ac[j][0];
            sFX[((2 * tig + 1) * 8 + k) * 128 + cl]     = ac[j][1];
            sFX[((2 * tig)     * 8 + k) * 128 + cl + 8] = ac[j][2];
            sFX[((2 * tig + 1) * 8 + k) * 128 + cl + 8] = ac[j][3];
        }
    }
}

// Stage C (v12 verbatim).
static __device__ __forceinline__ void tile_stageC(float* sFX, const float* sUm,
                                                   const float* sV, int t, int lane)
{
    u64t Fr0[8], Fr1[8];
#pragma unroll
    for (int k = 0; k < 8; k++) {
        float4 f = *(const float4*)(sFX + (t * 8 + k) * 128 + 4 * lane);
        Fr0[k] = pack2(f.x, f.y); Fr1[k] = pack2(f.z, f.w);
    }
    const float4 bq = *(const float4*)(sV + 128 + 4 * lane);
    const float4 gq = *(const float4*)(sV + 384 + 4 * lane);
    const float4 eq = *(const float4*)(sV + 512 + 4 * lane);
    const u64t b01 = pack2(bq.x, bq.y), b23 = pack2(bq.z, bq.w);

    u64t X20[8], X21[8];
#pragma unroll
    for (int k = 0; k < 8; k++) { X20[k] = 0ull; X21[k] = 0ull; }

#pragma unroll 4
    for (int n = 0; n < 64; n++) {
        float4 u0 = *(const float4*)(sUm + n * 8);
        float4 u1 = *(const float4*)(sUm + n * 8 + 4);
        u64t uk[8] = {dup2(u0.x), dup2(u0.y), dup2(u0.z), dup2(u0.w),
                      dup2(u1.x), dup2(u1.y), dup2(u1.z), dup2(u1.w)};
        u64t o0 = b01, o1 = b23;
#pragma unroll
        for (int k = 0; k < 8; k++) { fma2(o0, uk[k], Fr0[k]); fma2(o1, uk[k], Fr1[k]); }
        float a, b, c, d;
        unpack2(o0, a, b); unpack2(o1, c, d);
        float s = a + b + c + d;
        float s2 = a * a + b * b + c * c + d * d;
#pragma unroll
        for (int m = 1; m < 32; m <<= 1) {
            s  += __shfl_xor_sync(0xffffffffu, s, m);
            s2 += __shfl_xor_sync(0xffffffffu, s2, m);
        }
        const float mu = s * 0.0078125f;
        const float rstd = rsqrtf(s2 * 0.0078125f - mu * mu + 1e-5f);
        u64t hA = pack2(fmaxf((a - mu) * rstd * gq.x + eq.x, 0.f),
                        fmaxf((b - mu) * rstd * gq.y + eq.y, 0.f));
        u64t hB = pack2(fmaxf((c - mu) * rstd * gq.z + eq.z, 0.f),
                        fmaxf((d - mu) * rstd * gq.w + eq.w, 0.f));
#pragma unroll
        for (int k = 0; k < 8; k++) { fma2(X20[k], uk[k], hA); fma2(X21[k], uk[k], hB); }
    }
#pragma unroll
    for (int k = 0; k < 8; k++) {
        float a, b, c, d;
        unpack2(X20[k], a, b); unpack2(X21[k], c, d);
        *(float4*)(sFX + (t * 8 + k) * 128 + 4 * lane) = make_float4(a, b, c, d);
    }
}

// Stage E (v12 verbatim).
static __device__ __forceinline__ void tile_stageE(const float* sFX, const float* sUm,
                                                   const float* sV, const u64t* sWoB,
                                                   float* __restrict__ outg,
                                                   int t, int lane)
{
    u64t Fr0[8], Fr1[8];
#pragma unroll
    for (int k = 0; k < 8; k++) {
        float4 f = *(const float4*)(sFX + (t * 8 + k) * 128 + 4 * lane);
        Fr0[k] = pack2(f.x, f.y); Fr1[k] = pack2(f.z, f.w);
    }
    const float4 bq = *(const float4*)(sV + 256 + 4 * lane);
    const float4 gq = *(const float4*)(sV + 640 + 4 * lane);
    const float4 eq = *(const float4*)(sV + 768 + 4 * lane);
    const u64t b01 = pack2(bq.x, bq.y), b23 = pack2(bq.z, bq.w);

    u64t w2[4][4];
    {
        const int l7 = lane & 7;
#pragma unroll
        for (int u = 0; u < 8; u++) {
            int p = lane * 8 + (u ^ l7);
            u64t A = sWoB[2 * p], B = sWoB[2 * p + 1];
            const int j = u >> 1, qb = (u & 1) * 2;
            w2[j][qb] = A; w2[j][qb + 1] = B;
        }
    }
    const int g = lane >> 3;
    float2 boP = *(const float2*)(sV + 896 + 2 * g);

#pragma unroll 2
    for (int n = 0; n < 64; n++) {
        float4 u0 = *(const float4*)(sUm + n * 8);
        float4 u1 = *(const float4*)(sUm + n * 8 + 4);
        u64t uk[8] = {dup2(u0.x), dup2(u0.y), dup2(u0.z), dup2(u0.w),
                      dup2(u1.x), dup2(u1.y), dup2(u1.z), dup2(u1.w)};
        u64t o0 = b01, o1 = b23;
#pragma unroll
        for (int k = 0; k < 8; k++) { fma2(o0, uk[k], Fr0[k]); fma2(o1, uk[k], Fr1[k]); }
        float a, b, c, d;
        unpack2(o0, a, b); unpack2(o1, c, d);
        float s = a + b + c + d;
        float s2 = a * a + b * b + c * c + d * d;
#pragma unroll
        for (int m = 1; m < 32; m <<= 1) {
            s  += __shfl_xor_sync(0xffffffffu, s, m);
            s2 += __shfl_xor_sync(0xffffffffu, s2, m);
        }
        const float mu = s * 0.0078125f;
        const float rstd = rsqrtf(s2 * 0.0078125f - mu * mu + 1e-5f);
        float h0 = fmaxf((a - mu) * rstd * gq.x + eq.x, 0.f);
        float h1 = fmaxf((b - mu) * rstd * gq.y + eq.y, 0.f);
        float h2 = fmaxf((c - mu) * rstd * gq.z + eq.z, 0.f);
        float h3 = fmaxf((d - mu) * rstd * gq.w + eq.w, 0.f);

        u64t acc2[4] = {0ull, 0ull, 0ull, 0ull};
        u64t hb;
        hb = dup2(h0);
#pragma unroll
        for (int q = 0; q < 4; q++) fma2(acc2[q], hb, w2[0][q]);
        hb = dup2(h1);
#pragma unroll
        for (int q = 0; q < 4; q++) fma2(acc2[q], hb, w2[1][q]);
        hb = dup2(h2);
#pragma unroll
        for (int q = 0; q < 4; q++) fma2(acc2[q], hb, w2[2][q]);
        hb = dup2(h3);
#pragma unroll
        for (int q = 0; q < 4; q++) fma2(acc2[q], hb, w2[3][q]);

#pragma unroll
        for (int q = 0; q < 4; q++)
            acc2[q] = add2(acc2[q], __shfl_xor_sync(0xffffffffu, acc2[q], 16));
#pragma unroll
        for (int q = 0; q < 4; q++)
            acc2[q] = add2(acc2[q], __shfl_xor_sync(0xffffffffu, acc2[q], 8));
        u64t v = (g == 0) ? acc2[0] : (g == 1) ? acc2[1] : (g == 2) ? acc2[2] : acc2[3];
        v = add2(v, __shfl_xor_sync(0xffffffffu, v, 4));
        v = add2(v, __shfl_xor_sync(0xffffffffu, v, 2));
        v = add2(v, __shfl_xor_sync(0xffffffffu, v, 1));
        if ((lane & 7) == (n & 7)) {
            float x, y; unpack2(v, x, y);
            *(float2*)(outg + n * 8 + 2 * g) = make_float2(x + boP.x, y + boP.y);
        }
    }
}

__global__ void __launch_bounds__(NT, 2)
main_kernel(const float* __restrict__ x, const float* __restrict__ U,
            const float* __restrict__ Wp, const float* __restrict__ bp,
            const float* __restrict__ g1, const float* __restrict__ be1,
            const float* __restrict__ g3, const float* __restrict__ be3,
            const float* __restrict__ Wo, const float* __restrict__ bo,
            float* __restrict__ out)
{
    extern __shared__ float sm[];
    float* sFX  = sm + O_FX;
    float* sUm  = sm + O_UM;
    float* sWp  = sm + O_WP;
    float* sV   = sm + O_V;
    float* sY   = sm + O_Y;
    u64t*  sWoB = (u64t*)(sm + O_WOB);

    const int tid = threadIdx.x;
    const int wid = tid >> 5, lane = tid & 31;

    // ---- init: weights/vectors ----
    if (tid < 64) {
#pragma unroll
        for (int k = 0; k < 8; k++) sUm[tid * 8 + k] = U[tid * 64 + k];
    }
    for (int i = tid; i < 1024; i += NT) sWp[i] = Wp[i];
    if (tid < 128) {
        sV[tid]       = bp[tid];
        sV[128 + tid] = d_b1[tid];
        sV[256 + tid] = d_b3[tid];
        sV[384 + tid] = g1[tid];
        sV[512 + tid] = be1[tid];
        sV[640 + tid] = g3[tid];
        sV[768 + tid] = be3[tid];
    }
    if (tid < 8) { sV[896 + tid] = bo[tid]; sV[904 + tid] = d_tv[tid]; }
    if (tid < 256) {
        const int l = tid >> 3, u = (tid & 7) ^ (l & 7);
        const int j = u >> 1, qb = (u & 1) * 2;
        const int c = 4 * l + j;
        sWoB[2 * tid]     = pack2(Wo[c * 8 + 2 * qb],     Wo[c * 8 + 2 * qb + 1]);
        sWoB[2 * tid + 1] = pack2(Wo[c * 8 + 2 * qb + 2], Wo[c * 8 + 2 * qb + 3]);
    }
    __syncthreads();

    // ---- stage A pass 1: y[t][k][p] = sum_n Um[n,k] x[t][n][p] ----
    {
        const int k = lane >> 2, q = lane & 3;
        const float2* xg2 = (const float2*)(x + (size_t)blockIdx.x * 4096 + wid * 512);
        u64t acc = 0ull;
#pragma unroll 4
        for (int n = 0; n < 64; n++) {
            float um = sUm[n * 8 + k];
            float2 xv = __ldg(&xg2[n * 4 + q]);
            fma2(acc, dup2(um), pack2(xv.x, xv.y));
        }
        float a, b; unpack2(acc, a, b);
        *(float2*)(sY + wid * 64 + k * 8 + 2 * q) = make_float2(a, b);
    }
    __syncthreads();

    // ---- stage A pass 2: XF[t][k][c] = tv[k]*bp[c] + sum_p y[t][k][p] Wp[p][c] ----
    {
        const int k = wid, c4 = lane;
        const float tvk = sV[904 + k];
        const float4 bp4 = ((const float4*)sV)[c4];
#pragma unroll
        for (int t = 0; t < TT; t++) {
            const float* yv = sY + t * 64 + k * 8;
            u64t a01 = 0ull, a23 = 0ull;
            u64t tb = dup2(tvk);
            fma2(a01, tb, pack2(bp4.x, bp4.y));
            fma2(a23, tb, pack2(bp4.z, bp4.w));
#pragma unroll
            for (int p = 0; p < 8; p++) {
                u64t yb = dup2(yv[p]);
                float4 wp = ((const float4*)(sWp + p * 128))[c4];
                fma2(a01, yb, pack2(wp.x, wp.y));
                fma2(a23, yb, pack2(wp.z, wp.w));
            }
            float a, b, c, d;
            unpack2(a01, a, b); unpack2(a23, c, d);
            *(float4*)(sFX + (t * 8 + k) * 128 + 4 * c4) = make_float4(a, b, c, d);
        }
    }

    // ---- stage B: f0 via tensor cores (in place) ----
    mode_gemm(d_MA0h, d_MA0l, sFX, tid);
    __syncthreads();

    // ---- stage C ----
    tile_stageC(sFX, sUm, sV, wid, lane);
    __syncthreads();

    // ---- stage D: f2 via tensor cores (in place) ----
    mode_gemm(d_MA2h, d_MA2l, sFX, tid);
    __syncthreads();

    // ---- stage E ----
    float* outg = out + (size_t)blockIdx.x * 4096;
    tile_stageE(sFX, sUm, sV, sWoB, outg + wid * 512, wid, lane);
}

// ------------------------------- launch ------------------------------------

extern "C" void kernel_launch(void* const* d_in, const int* in_sizes, int n_in,
                              void* d_out, int out_size)
{
    const float* x   = (const float*)d_in[0];
    const float* adj = (const float*)d_in[1];
    const float* U   = (const float*)d_in[2];
    const float* Wp  = (const float*)d_in[3];
    const float* bp  = (const float*)d_in[4];
    const float* w0  = (const float*)d_in[5];
    const float* w2  = (const float*)d_in[6];
    const float* Ws1 = (const float*)d_in[7];
    const float* bs1 = (const float*)d_in[8];
    const float* Wn1 = (const float*)d_in[9];
    const float* bn1 = (const float*)d_in[10];
    const float* g1  = (const float*)d_in[11];
    const float* be1 = (const float*)d_in[12];
    const float* Ws3 = (const float*)d_in[13];
    const float* bs3 = (const float*)d_in[14];
    const float* Wn3 = (const float*)d_in[15];
    const float* bn3 = (const float*)d_in[16];
    const float* g3  = (const float*)d_in[17];
    const float* be3 = (const float*)d_in[18];
    const float* Wo  = (const float*)d_in[19];
    const float* bo  = (const float*)d_in[20];
    float* out = (float*)d_out;

    pre_kernel<<<256, 128>>>(U, adj, w0, w2, Ws1, Wn1, Ws3, Wn3,
                             bs1, bn1, bs3, bn3);

    const size_t smem = SMEMF * sizeof(float);  // 48 KB -> 2 CTAs/SM
    cudaFuncSetAttribute(main_kernel, cudaFuncAttributeMaxDynamicSharedMemorySize,
                         (int)smem);
    main_kernel<<<2048, NT, smem>>>(x, U, Wp, bp, g1, be1, g3, be3, Wo, bo, out);
}